// round 2
// baseline (speedup 1.0000x reference)
#include <cuda_runtime.h>
#include <cstdint>

#define FEATURE_COUNT 106496LL
#define ACCUM 256
#define LEAK 0.1f
#define MAX_STAGE 32

// ---------------------------------------------------------------------------
// int64-vs-int32 detection (reference asks for int64; JAX x64 config may give
// int32). 16 samples read as int64 must all be valid feature indices.
// ---------------------------------------------------------------------------
__device__ int g_is64;

__global__ void detect_dtype_kernel(const void* __restrict__ idx) {
    if (threadIdx.x == 0 && blockIdx.x == 0) {
        const long long* p = (const long long*)idx;
        int ok = 1;
        #pragma unroll
        for (int k = 0; k < 16; k++) {
            long long v = p[k];
            if (v < 0 || v >= FEATURE_COUNT) ok = 0;
        }
        g_is64 = ok;
    }
}

__device__ __forceinline__ long long geti(const void* p, long long i, int is64) {
    return is64 ? ((const long long*)p)[i] : (long long)((const int*)p)[i];
}

__device__ __forceinline__ float clipped_relu(float x) {
    float c = fminf(fmaxf(x, -1.0f), 127.0f / 128.0f);
    return c + LEAK * (x - c);
}

__device__ __forceinline__ uint32_t smem_u32(const void* p) {
    uint32_t a;
    asm("{ .reg .u64 t; cvta.to.shared.u64 t, %1; cvt.u32.u64 %0, t; }"
        : "=r"(a) : "l"(p));
    return a;
}

// ---------------------------------------------------------------------------
// One block (128 threads) per batch.
//   1. 32 lanes issue cp.async.bulk: row j (1KB) -> smem stage  (UBLKCP path,
//      bypasses L1tex queue / per-thread scoreboards)
//   2. mbarrier expect_tx = cnt*1024, all threads wait
//   3. thread t sums columns {2t, 2t+1} over the staged rows (+bias)
//   4. selected model's 3-layer MLP + tanh epilogue
// ---------------------------------------------------------------------------
__global__ __launch_bounds__(128) void nnue_kernel(
    const void*  __restrict__ indices,
    const void*  __restrict__ offsets,
    const void*  __restrict__ which_model,
    const void*  __restrict__ lengths,
    const float* __restrict__ embed,
    const float* __restrict__ bias,
    const float* __restrict__ W1, const float* __restrict__ b1,
    const float* __restrict__ W2, const float* __restrict__ b2,
    const float* __restrict__ W3, const float* __restrict__ b3,
    float* __restrict__ out,
    long long n_idx, int B)
{
    __shared__ __align__(1024) float s_stage[MAX_STAGE * ACCUM];  // 32 KB
    __shared__ __align__(16)   float s_emb[ACCUM];
    __shared__ float s_h1[16];
    __shared__ float s_psqt;
    __shared__ int   s_sel;
    __shared__ __align__(8) unsigned long long s_mbar;

    const int t = threadIdx.x;
    const int b = blockIdx.x;
    const int is64 = g_is64;

    const long long lo = geti(offsets, b, is64);
    const long long hi = (b + 1 < B) ? geti(offsets, b + 1, is64) : n_idx;
    const int cnt = (int)(hi - lo);
    const int staged = cnt < MAX_STAGE ? cnt : MAX_STAGE;

    const uint32_t mbar = smem_u32(&s_mbar);

    if (t == 0) {
        asm volatile("mbarrier.init.shared.b64 [%0], %1;"
                     :: "r"(mbar), "r"(1) : "memory");
        // expect_tx is also the single arrival; posted before any copy issues.
        asm volatile("mbarrier.arrive.expect_tx.shared.b64 _, [%0], %1;"
                     :: "r"(mbar), "r"((unsigned)(staged * 1024)) : "memory");
        // model selection, overlapped with the copies
        int wm = (int)geti(which_model, b, is64);
        int le = (int)geti(lengths, b, is64);
        s_sel = wm + (le / 17) * 4;
    }
    __syncthreads();

    // issue bulk copies: lane j handles rows j, j+32, ...
    const uint32_t stage_base = smem_u32(s_stage);
    if (t < 32) {
        for (int j = t; j < staged; j += 32) {
            long long id = geti(indices, lo + j, is64);
            const float* src = embed + id * ACCUM;
            uint32_t dst = stage_base + (uint32_t)j * (ACCUM * 4);
            asm volatile(
                "cp.async.bulk.shared::cta.global.mbarrier::complete_tx::bytes "
                "[%0], [%1], %2, [%3];"
                :: "r"(dst), "l"(src), "r"(ACCUM * 4), "r"(mbar) : "memory");
        }
    }

    // wait for all staged rows
    {
        uint32_t done;
        asm volatile(
            "{\n\t.reg .pred p;\n\t"
            "mbarrier.try_wait.parity.acquire.cta.shared::cta.b64 p, [%1], %2;\n\t"
            "selp.b32 %0, 1, 0, p;\n\t}"
            : "=r"(done) : "r"(mbar), "r"(0) : "memory");
        while (!done) {
            asm volatile(
                "{\n\t.reg .pred p;\n\t"
                "mbarrier.try_wait.parity.acquire.cta.shared::cta.b64 p, [%1], %2, 0x989680;\n\t"
                "selp.b32 %0, 1, 0, p;\n\t}"
                : "=r"(done) : "r"(mbar), "r"(0) : "memory");
        }
    }

    // ---- accumulate: thread t owns columns 2t, 2t+1 ----
    float2 acc = ((const float2*)bias)[t];
    #pragma unroll 8
    for (int r = 0; r < staged; r++) {
        float2 v = *(const float2*)&s_stage[r * ACCUM + 2 * t];
        acc.x += v.x; acc.y += v.y;
    }
    // generic tail: rows beyond the staging capacity read directly
    for (int r = MAX_STAGE; r < cnt; r++) {
        long long id = geti(indices, lo + r, is64);
        float2 v = *(const float2*)(embed + id * ACCUM + 2 * t);
        acc.x += v.x; acc.y += v.y;
    }

    if (t == 0) s_psqt = acc.x;                 // pre-activation column 0
    s_emb[2 * t]     = clipped_relu(acc.x);
    s_emb[2 * t + 1] = clipped_relu(acc.y);
    __syncthreads();

    const int sel = s_sel;

    // ---- layer 1: 16 outputs, 8 lanes each (each lane sums 32 of 256) ----
    {
        const int o = t >> 3;
        const int k = t & 7;
        const float4* __restrict__ w =
            (const float4*)(W1 + ((long long)sel * 16 + o) * ACCUM) + k * 8;
        const float4* __restrict__ e = (const float4*)s_emb + k * 8;
        float s = 0.0f;
        #pragma unroll
        for (int j = 0; j < 8; j++) {
            float4 wv = w[j], ev = e[j];
            s += wv.x * ev.x + wv.y * ev.y + wv.z * ev.z + wv.w * ev.w;
        }
        s += __shfl_xor_sync(0xffffffffu, s, 1);
        s += __shfl_xor_sync(0xffffffffu, s, 2);
        s += __shfl_xor_sync(0xffffffffu, s, 4);
        if (k == 0) s_h1[o] = clipped_relu(s + b1[sel * 16 + o]);
    }
    __syncthreads();

    // ---- layers 2+3 + epilogue (warp 0) ----
    if (t < 32) {
        const float* __restrict__ w2 = W2 + ((long long)sel * 32 + t) * 16;
        float s = b2[sel * 32 + t];
        #pragma unroll
        for (int j = 0; j < 16; j++) s += w2[j] * s_h1[j];
        float p = clipped_relu(s) * W3[sel * 32 + t];
        #pragma unroll
        for (int off = 16; off > 0; off >>= 1)
            p += __shfl_xor_sync(0xffffffffu, p, off);
        if (t == 0)
            out[b] = tanhf(p + b3[sel] + s_psqt);
    }
}

extern "C" void kernel_launch(void* const* d_in, const int* in_sizes, int n_in,
                              void* d_out, int out_size) {
    const void*  indices     = d_in[0];
    const void*  offsets     = d_in[1];
    const void*  which_model = d_in[2];
    const void*  lengths     = d_in[3];
    const float* embed       = (const float*)d_in[4];
    const float* bias        = (const float*)d_in[5];
    const float* W1 = (const float*)d_in[6];
    const float* b1 = (const float*)d_in[7];
    const float* W2 = (const float*)d_in[8];
    const float* b2 = (const float*)d_in[9];
    const float* W3 = (const float*)d_in[10];
    const float* b3 = (const float*)d_in[11];

    long long n_idx = in_sizes[0];
    int B = in_sizes[1];

    detect_dtype_kernel<<<1, 1>>>(indices);
    nnue_kernel<<<B, 128>>>(indices, offsets, which_model, lengths,
                            embed, bias, W1, b1, W2, b2, W3, b3,
                            (float*)d_out, n_idx, B);
}